// round 10
// baseline (speedup 1.0000x reference)
#include <cuda_runtime.h>
#include <cuda_fp16.h>

#define N_NODES 100000
#define N_FEATS 512
#define HIDDEN  64
#define NSAMP   5
#define NCLS    16
#define NBATCH  16384

typedef unsigned int u32;

// ---------------- scratch (static device globals) ---------------------------
__device__ __half g_W1[128 * N_FEATS];   // [n=0..127][k] row-major fp16
__device__ __half g_W2[128 * HIDDEN];
__device__ __half g_Wc[32 * HIDDEN];     // rows 0-15: wcls hi, rows 16-31: wcls lo
__device__ __half g_PG[(size_t)N_NODES * 128];      // P | G  (fp16)
__device__ __half g_UV[(size_t)N_NODES * 128];      // U | V  (fp16)

// ---------------- helpers ----------------------------------------------------
__device__ __forceinline__ u32 smem_u32(const void* p) {
    u32 a;
    asm("{ .reg .u64 t; cvta.to.shared.u64 t, %1; cvt.u32.u64 %0, t; }"
        : "=r"(a) : "l"(p));
    return a;
}
__device__ __forceinline__ void ldsm4(u32& r0, u32& r1, u32& r2, u32& r3, u32 addr) {
    asm volatile("ldmatrix.sync.aligned.m8n8.x4.shared.b16 {%0,%1,%2,%3}, [%4];"
                 : "=r"(r0), "=r"(r1), "=r"(r2), "=r"(r3) : "r"(addr));
}
__device__ __forceinline__ void mma_f16(float* d, const u32* a, const u32* b) {
    asm volatile(
        "mma.sync.aligned.m16n8k16.row.col.f32.f16.f16.f32 "
        "{%0,%1,%2,%3}, {%4,%5,%6,%7}, {%8,%9}, {%0,%1,%2,%3};"
        : "+f"(d[0]), "+f"(d[1]), "+f"(d[2]), "+f"(d[3])
        : "r"(a[0]), "r"(a[1]), "r"(a[2]), "r"(a[3]), "r"(b[0]), "r"(b[1]));
}
__device__ __forceinline__ void cpasync16(u32 dst, const void* src, int srcsize) {
    asm volatile("cp.async.cg.shared.global [%0], [%1], 16, %2;"
                 :: "r"(dst), "l"(src), "r"(srcsize) : "memory");
}
__device__ __forceinline__ void cpcommit() {
    asm volatile("cp.async.commit_group;" ::: "memory");
}
template <int N>
__device__ __forceinline__ void cpwait() {
    asm volatile("cp.async.wait_group %0;" :: "n"(N) : "memory");
}
#define SW128(x) ((x) ^ (((x) >> 3) & 0x70))
#define SW64(x)  ((x) ^ (((x) >> 3) & 0x30))

// ---------------------------------------------------------------------------
// Weight prep: W1/W2 fp16 ([n][k] row-major; n<64 self, n>=64 neighbor block),
// wcls split into fp16 hi/lo rows.
// ---------------------------------------------------------------------------
__global__ void prep_weights(const float* __restrict__ w1, const float* __restrict__ w2,
                             const float* __restrict__ wcls) {
    int idx = blockIdx.x * 256 + threadIdx.x;
    if (idx < 128 * N_FEATS) {
        int n = idx / N_FEATS, k = idx % N_FEATS;
        float v = (n < 64) ? w1[n * (2 * N_FEATS) + k]
                           : w1[(n - 64) * (2 * N_FEATS) + N_FEATS + k];
        g_W1[idx] = __float2half_rn(v);
    }
    if (idx < 128 * HIDDEN) {
        int n = idx / HIDDEN, k = idx % HIDDEN;
        float v = (n < 64) ? w2[n * (2 * HIDDEN) + k]
                           : w2[(n - 64) * (2 * HIDDEN) + HIDDEN + k];
        g_W2[idx] = __float2half_rn(v);
    }
    if (idx < NCLS * HIDDEN) {
        float v = wcls[idx];
        __half h = __float2half_rn(v);
        g_Wc[idx] = h;
        g_Wc[NCLS * HIDDEN + idx] = __float2half_rn(v - __half2float(h));
    }
}

// ===========================================================================
// GEMM1: C[M,128] (fp16) = A[M,512] (fp32, converted in smem) @ W1[128,512]^T
// 128x128 CTA tile, 4 warps (64x64 warp tiles -> 2 readers per A/B row),
// KC=32. Ring: 3 A-fp32 stages, 4 B stages, 2 fp16 work bufs.
// One __syncthreads per chunk; convert(t+1) overlaps MMA(t).
// ===========================================================================
#define KC1   32
#define NCH1  (N_FEATS / KC1)          // 16
#define A1_OFF   0                      // 3 x 16384
#define A1_BYTES 16384
#define B1_OFF   49152                  // 4 x 8192
#define B1_BYTES 8192
#define W1_OFF   81920                  // 2 x 8192
#define W1_BYTES 8192
#define G1_SMEM  98304                  // 96 KB

__global__ __launch_bounds__(128, 2)
void gemm1_tc(const float* __restrict__ Af, const __half* __restrict__ Bm,
              __half* __restrict__ Cm, int M) {
    extern __shared__ __align__(1024) char smem[];
    const u32 sb = smem_u32(smem);
    const int tid  = threadIdx.x;
    const int wid  = tid >> 5;
    const int lane = tid & 31;
    const int wm   = (wid & 1) * 64;       // 2 M-positions
    const int wn   = (wid >> 1) * 64;      // 2 N-positions
    const int row0 = blockIdx.x * 128;

    // loader coords: one 128B A row / one 64B B row per thread
    const int lrow = tid;                  // 0..127
    const bool arow_ok = (row0 + lrow) < M;
    const u32 aoff = (u32)lrow * 128;      // A stage byte offset (fp32 row)
    const u32 woff = (u32)lrow * 64;       // fp16 row byte offset

    auto issue_stage = [&](int c) {
        u32 abase = sb + A1_OFF + (c % 3) * A1_BYTES;
        u32 bbase = sb + B1_OFF + (c & 3) * B1_BYTES;
        int k0 = c * KC1;
        const float* asrc = Af + (size_t)(arow_ok ? row0 + lrow : 0) * N_FEATS + k0;
        int sz = arow_ok ? 16 : 0;
#pragma unroll
        for (int j = 0; j < 8; j++)
            cpasync16(abase + SW128(aoff + j * 16), asrc + j * 4, sz);
        const __half* bsrc = Bm + (size_t)lrow * N_FEATS + k0;
#pragma unroll
        for (int j = 0; j < 4; j++)
            cpasync16(bbase + SW64(woff + j * 16), bsrc + j * 8, 16);
        cpcommit();
    };

    auto convert = [&](int c) {
        char* astage = smem + A1_OFF + (c % 3) * A1_BYTES;
        char* wbase  = smem + W1_OFF + (c & 1) * W1_BYTES;
#pragma unroll
        for (int j = 0; j < 4; j++) {
            float4 v0 = *(const float4*)(astage + SW128(aoff + j * 32));
            float4 v1 = *(const float4*)(astage + SW128(aoff + j * 32 + 16));
            __half2 p0 = __floats2half2_rn(v0.x, v0.y);
            __half2 p1 = __floats2half2_rn(v0.z, v0.w);
            __half2 p2 = __floats2half2_rn(v1.x, v1.y);
            __half2 p3 = __floats2half2_rn(v1.z, v1.w);
            *(uint4*)(wbase + SW64(woff + j * 16)) =
                make_uint4(*(u32*)&p0, *(u32*)&p1, *(u32*)&p2, *(u32*)&p3);
        }
    };

    // ldmatrix lane coords
    const int grp = lane >> 3, lr = lane & 7;
    const int a_m  = wm + (grp & 1) * 8 + lr;
    const int a_kb = (grp >> 1) * 16;
    const int b_n  = wn + (grp >> 1) * 8 + lr;
    const int b_kb = (grp & 1) * 16;

    float acc[4][8][4];
#pragma unroll
    for (int i = 0; i < 4; i++)
#pragma unroll
        for (int j = 0; j < 8; j++)
#pragma unroll
            for (int c = 0; c < 4; c++) acc[i][j][c] = 0.f;

    issue_stage(0);
    issue_stage(1);
    issue_stage(2);
    cpwait<2>();          // chunk 0 arrived
    convert(0);

    for (int t = 0; t < NCH1; ++t) {
        __syncthreads();  // publish wrk[t&1] + B[t]; all reads of t-1 done

        if (t + 3 < NCH1) issue_stage(t + 3);

        if (t + 3 < NCH1)      cpwait<2>();
        else if (t + 2 < NCH1) cpwait<1>();
        else                   cpwait<0>();

        if (t + 1 < NCH1) convert(t + 1);   // overlaps MMA(t)

        u32 sW = sb + W1_OFF + (t & 1) * W1_BYTES;
        u32 sB = sb + B1_OFF + (t & 3) * B1_BYTES;

#pragma unroll
        for (int ks = 0; ks < 2; ks++) {
            u32 a4[4][4];
#pragma unroll
            for (int mt = 0; mt < 4; mt++) {
                u32 off = SW64((u32)((a_m + mt * 16) * 64 + ks * 32 + a_kb));
                ldsm4(a4[mt][0], a4[mt][1], a4[mt][2], a4[mt][3], sW + off);
            }
            // process B in two halves (nt 0-3, then 4-7) to bound register liveness
#pragma unroll
            for (int half = 0; half < 2; half++) {
                u32 b4[4][2];
#pragma unroll
                for (int p = 0; p < 2; p++) {
                    u32 off = SW64((u32)((b_n + half * 32 + p * 16) * 64 + ks * 32 + b_kb));
                    u32 r0, r1, r2, r3;
                    ldsm4(r0, r1, r2, r3, sB + off);
                    b4[2 * p][0] = r0; b4[2 * p][1] = r1;
                    b4[2 * p + 1][0] = r2; b4[2 * p + 1][1] = r3;
                }
#pragma unroll
                for (int mt = 0; mt < 4; mt++)
#pragma unroll
                    for (int nt = 0; nt < 4; nt++)
                        mma_f16(acc[mt][half * 4 + nt], a4[mt], b4[nt]);
            }
        }
    }

    // epilogue: fp16 output
    const int tm = lane >> 2;
    const int tn = (lane & 3) * 2;
#pragma unroll
    for (int mt = 0; mt < 4; mt++) {
        int gm0 = row0 + wm + mt * 16 + tm;
#pragma unroll
        for (int nt = 0; nt < 8; nt++) {
            int gn = wn + nt * 8 + tn;
            __half2 v01 = __floats2half2_rn(acc[mt][nt][0], acc[mt][nt][1]);
            __half2 v23 = __floats2half2_rn(acc[mt][nt][2], acc[mt][nt][3]);
            if (gm0 < M)     *(__half2*)(Cm + (size_t)gm0 * 128 + gn) = v01;
            if (gm0 + 8 < M) *(__half2*)(Cm + (size_t)(gm0 + 8) * 128 + gn) = v23;
        }
    }
}

// ===========================================================================
// GEMM2 fused with layer-1 aggregation:
//   A[r] = relu(P[n] + 0.2 * sum_s G[neigh[n,s]])  built in smem from g_PG,
//   C[M,128] (fp16) = A[M,64] @ W2[128,64]^T.
// ===========================================================================
#define G2_OFFA 0
#define G2_OFFB 16384
#define G2_SMEM 32768

__global__ __launch_bounds__(256, 2)
void gemm2_fused(const int* __restrict__ neigh, const __half* __restrict__ Bm,
                 __half* __restrict__ Cm, int M) {
    extern __shared__ __align__(1024) char smem[];
    const u32 sb = smem_u32(smem);
    const int tid  = threadIdx.x;
    const int wid  = tid >> 5;
    const int lane = tid & 31;
    const int wm   = (wid & 1) * 64;
    const int wn   = (wid >> 1) * 32;
    const int row0 = blockIdx.x * 128;

    const int lrow  = tid >> 1;
    const int lhalf = tid & 1;
    const u32 rowoff = (u32)lrow * 128 + (u32)lhalf * 64;
    const int n = row0 + lrow;
    const bool arow_ok = n < M;

    // --- B tile via cp.async (overlaps the gather) ---
    {
        u32 bbase = sb + G2_OFFB;
        const __half* bsrc = Bm + (size_t)lrow * HIDDEN + lhalf * 32;
#pragma unroll
        for (int j = 0; j < 4; j++)
            cpasync16(bbase + SW128(rowoff + j * 16), bsrc + j * 8, 16);
        cpcommit();
    }

    // --- A tile: fused aggregation from g_PG (L2-resident) ---
    {
        float val[32];
#pragma unroll
        for (int e = 0; e < 32; e++) val[e] = 0.f;

        if (arow_ok) {
#pragma unroll
            for (int s = 0; s < NSAMP; s++) {
                int nb = __ldg(&neigh[n * NSAMP + s]);
                const uint4* src = (const uint4*)(g_PG + (size_t)nb * 128 + 64 + lhalf * 32);
#pragma unroll
                for (int j = 0; j < 4; j++) {
                    uint4 v = __ldg(src + j);
                    u32 w[4] = {v.x, v.y, v.z, v.w};
#pragma unroll
                    for (int q = 0; q < 4; q++) {
                        __half2 h = *(__half2*)&w[q];
                        val[j * 8 + q * 2]     += __low2float(h);
                        val[j * 8 + q * 2 + 1] += __high2float(h);
                    }
                }
            }
            const uint4* sp = (const uint4*)(g_PG + (size_t)n * 128 + lhalf * 32);
#pragma unroll
            for (int j = 0; j < 4; j++) {
                uint4 v = __ldg(sp + j);
                u32 w[4] = {v.x, v.y, v.z, v.w};
#pragma unroll
                for (int q = 0; q < 4; q++) {
                    __half2 h = *(__half2*)&w[q];
                    int e = j * 8 + q * 2;
                    val[e]     = fmaxf(fmaf(val[e],     0.2f, __low2float(h)),  0.f);
                    val[e + 1] = fmaxf(fmaf(val[e + 1], 0.2f, __high2float(h)), 0.f);
                }
            }
        }

        char* abase = smem + G2_OFFA;
#pragma unroll
        for (int j = 0; j < 4; j++) {
            __half2 p0 = __floats2half2_rn(val[j * 8 + 0], val[j * 8 + 1]);
            __half2 p1 = __floats2half2_rn(val[j * 8 + 2], val[j * 8 + 3]);
            __half2 p2 = __floats2half2_rn(val[j * 8 + 4], val[j * 8 + 5]);
            __half2 p3 = __floats2half2_rn(val[j * 8 + 6], val[j * 8 + 7]);
            *(uint4*)(abase + SW128(rowoff + j * 16)) =
                make_uint4(*(u32*)&p0, *(u32*)&p1, *(u32*)&p2, *(u32*)&p3);
        }
    }

    cpwait<0>();
    __syncthreads();

    const int grp = lane >> 3, lr = lane & 7;
    const int a_m  = wm + (grp & 1) * 8 + lr;
    const int a_kb = (grp >> 1) * 16;
    const int b_n  = wn + (grp >> 1) * 8 + lr;
    const int b_kb = (grp & 1) * 16;

    float acc[4][4][4];
#pragma unroll
    for (int i = 0; i < 4; i++)
#pragma unroll
        for (int j = 0; j < 4; j++)
#pragma unroll
            for (int c = 0; c < 4; c++) acc[i][j][c] = 0.f;

    u32 sA = sb + G2_OFFA, sB = sb + G2_OFFB;
#pragma unroll
    for (int ks = 0; ks < 4; ks++) {
        u32 a4[4][4];
#pragma unroll
        for (int mt = 0; mt < 4; mt++) {
            u32 off = SW128((u32)((a_m + mt * 16) * 128 + ks * 32 + a_kb));
            ldsm4(a4[mt][0], a4[mt][1], a4[mt][2], a4[mt][3], sA + off);
        }
        u32 b4[4][2];
#pragma unroll
        for (int p = 0; p < 2; p++) {
            u32 off = SW128((u32)((b_n + p * 16) * 128 + ks * 32 + b_kb));
            u32 r0, r1, r2, r3;
            ldsm4(r0, r1, r2, r3, sB + off);
            b4[2 * p][0] = r0; b4[2 * p][1] = r1;
            b4[2 * p + 1][0] = r2; b4[2 * p + 1][1] = r3;
        }
#pragma unroll
        for (int mt = 0; mt < 4; mt++)
#pragma unroll
            for (int nt = 0; nt < 4; nt++)
                mma_f16(acc[mt][nt], a4[mt], b4[nt]);
    }

    const int tm = lane >> 2;
    const int tn = (lane & 3) * 2;
#pragma unroll
    for (int mt = 0; mt < 4; mt++) {
        int gm0 = row0 + wm + mt * 16 + tm;
#pragma unroll
        for (int nt = 0; nt < 4; nt++) {
            int gn = wn + nt * 8 + tn;
            __half2 v01 = __floats2half2_rn(acc[mt][nt][0], acc[mt][nt][1]);
            __half2 v23 = __floats2half2_rn(acc[mt][nt][2], acc[mt][nt][3]);
            if (gm0 < M)     *(__half2*)(Cm + (size_t)gm0 * 128 + gn) = v01;
            if (gm0 + 8 < M) *(__half2*)(Cm + (size_t)(gm0 + 8) * 128 + gn) = v23;
        }
    }
}

// ===========================================================================
// Final fused: h2 = relu(U[n] + 0.2*sum_s V[nb]) -> [128,64] fp16 smem tile,
// out[128,16] = h2 @ (Wc_hi + Wc_lo)^T via HMMA. 128 CTAs x 256 thr.
// ===========================================================================
#define FN_OFFA 0
#define FN_OFFB 16384
#define FN_SMEM 20480

__global__ __launch_bounds__(256)
void final_fused(const int* __restrict__ nodes, const int* __restrict__ neigh,
                 float* __restrict__ out) {
    extern __shared__ __align__(1024) char smem[];
    const u32 sb = smem_u32(smem);
    const int tid  = threadIdx.x;
    const int wid  = tid >> 5;
    const int lane = tid & 31;
    const int row0 = blockIdx.x * 128;

    // --- B: wcls hi/lo, 32 rows x 128B, via cp.async ---
    if (tid < 64) {
        int r = tid >> 1, h = tid & 1;
        const __half* src = g_Wc + r * HIDDEN + h * 32;
        u32 bbase = sb + FN_OFFB;
        u32 roff = (u32)r * 128 + (u32)h * 64;
#pragma unroll
        for (int j = 0; j < 4; j++)
            cpasync16(bbase + SW128(roff + j * 16), src + j * 8, 16);
    }
    cpcommit();

    // --- A: gather + aggregate h2 row (2 threads per element) ---
    {
        const int lrow  = tid >> 1;
        const int lhalf = tid & 1;
        const int b = row0 + lrow;
        const int n = __ldg(&nodes[b]);

        float val[32];
#pragma unroll
        for (int e = 0; e < 32; e++) val[e] = 0.f;

#pragma unroll
        for (int s = 0; s < NSAMP; s++) {
            int nb = __ldg(&neigh[n * NSAMP + s]);
            const uint4* src = (const uint4*)(g_UV + (size_t)nb * 128 + 64 + lhalf * 32);
#pragma unroll
            for (int j = 0; j < 4; j++) {
                uint4 v = __ldg(src + j);
                u32 w[4] = {v.x, v.y, v.z, v.w};
#pragma unroll
                for (int q = 0; q < 4; q++) {
                    __half2 hh = *(__half2*)&w[q];
                    val[j * 8 + q * 2]     += __low2float(hh);
                    val[j * 8 + q * 2 + 1] += __high2float(hh);
                }
            }
        }
        const uint4* sp = (const uint4*)(g_UV + (size_t)n * 128 + lhalf * 32);
#pragma unroll
        for (int j = 0; j < 4; j++) {
            uint4 v = __ldg(sp + j);
            u32 w[4] = {v.x, v.y, v.z, v.w};
#pragma unroll
            for (int q = 0; q < 4; q++) {
                __half2 hh = *(__half2*)&w[q];
                int e = j * 8 + q * 2;
                val[e]     = fmaxf(fmaf(val[e],     0.2f, __low2float(hh)),  0.f);
                val[e + 1] = fmaxf(fmaf(val[e + 1], 0.2f, __high2float(hh)), 0.f);
            }
        }

        char* abase = smem + FN_OFFA;
        u32 roff = (u32)lrow * 128 + (u32)lhalf * 64;
#pragma unroll
        for (int j = 0; j < 4; j++) {
            __half2 p0 = __floats2half2_rn(val[j * 8 + 0], val[j * 8 + 1]);
            __half2 p1 = __floats2half2_rn(val[j * 8 + 2], val[j * 8 + 3]);
            __half2 p2 = __floats2half2_rn(val[j * 8 + 4], val[j * 8 + 5]);
            __half2 p3 = __floats2half2_rn(val[j * 8 + 6], val[j * 8 + 7]);
            *(uint4*)(abase + SW128(roff + j * 16)) =
                make_uint4(*(u32*)&p0, *(u32*)&p1, *(u32*)&p2, *(u32*)&p3);
        }
    }

    cpwait<0>();
    __syncthreads();

    const int grp = lane >> 3, lr = lane & 7;
    const int a_m  = wid * 16 + (grp & 1) * 8 + lr;
    const int a_kb = (grp >> 1) * 16;
    const int b_n  = (grp >> 1) * 8 + lr;
    const int b_kb = (grp & 1) * 16;

    float acc[2][4];
#pragma unroll
    for (int i = 0; i < 2; i++)
#pragma unroll
        for (int c = 0; c < 4; c++) acc[i][c] = 0.f;

    u32 sA = sb + FN_OFFA, sB = sb + FN_OFFB;
#pragma unroll
    for (int ks = 0; ks < 4; ks++) {
        u32 a4[4];
        {
            u32 off = SW128((u32)(a_m * 128 + ks * 32 + a_kb));
            ldsm4(a4[0], a4[1], a4[2], a4[3], sA + off);
        }
        u32 bh[2][2], bl[2][2];
        {
            u32 off = SW128((u32)(b_n * 128 + ks * 32 + b_kb));
            u32 r0, r1, r2, r3;
            ldsm4(r0, r1, r2, r3, sB + off);
            bh[0][0] = r0; bh[0][1] = r1; bh[1][0] = r2; bh[1][1] = r3;
            ldsm4(r0, r1, r2, r3, sB + 2048 + off);
            bl[0][0] = r0; bl[0][1] = r1; bl[1][0] = r2; bl[1][1] = r3;
        }
#pragma unroll
        for (int nt = 0; nt < 2; nt++) {
            mma_f16(acc[nt], a4, bh[nt]);
            mma_f16(acc[nt], a4, bl[nt]);
        }
    }

    const int tm = lane >> 2;
    const int tn = (lane & 3) * 2;
    int gm0 = row0 + wid * 16 + tm;
#pragma unroll
    for (int nt = 0; nt < 2; nt++) {
        int gn = nt * 8 + tn;
        *(float2*)(out + (size_t)gm0 * NCLS + gn)       = make_float2(acc[nt][0], acc[nt][1]);
        *(float2*)(out + (size_t)(gm0 + 8) * NCLS + gn) = make_float2(acc[nt][2], acc[nt][3]);
    }
}

// ---------------------------------------------------------------------------
extern "C" void kernel_launch(void* const* d_in, const int* in_sizes, int n_in,
                              void* d_out, int out_size) {
    const float* features = (const float*)d_in[0];
    const float* w1       = (const float*)d_in[1];
    const float* w2       = (const float*)d_in[2];
    const float* wcls     = (const float*)d_in[3];
    const int*   nodes    = (const int*)d_in[4];
    const int*   neigh    = (const int*)d_in[5];
    float*       out      = (float*)d_out;

    __half *pW1, *pW2, *pPG, *pUV;
    cudaGetSymbolAddress((void**)&pW1, g_W1);
    cudaGetSymbolAddress((void**)&pW2, g_W2);
    cudaGetSymbolAddress((void**)&pPG, g_PG);
    cudaGetSymbolAddress((void**)&pUV, g_UV);

    cudaFuncSetAttribute(gemm1_tc, cudaFuncAttributeMaxDynamicSharedMemorySize, G1_SMEM);
    cudaFuncSetAttribute(gemm2_fused, cudaFuncAttributeMaxDynamicSharedMemorySize, G2_SMEM);
    cudaFuncSetAttribute(final_fused, cudaFuncAttributeMaxDynamicSharedMemorySize, FN_SMEM);

    const int gemm_blocks = (N_NODES + 127) / 128;   // 782

    prep_weights<<<(128 * N_FEATS + 255) / 256, 256>>>(w1, w2, wcls);
    gemm1_tc<<<gemm_blocks, 128, G1_SMEM>>>(features, pW1, pPG, N_NODES);
    gemm2_fused<<<gemm_blocks, 256, G2_SMEM>>>(neigh, pW2, pUV, N_NODES);
    final_fused<<<NBATCH / 128, 256, FN_SMEM>>>(nodes, neigh, out);
}

// round 11
// speedup vs baseline: 1.3806x; 1.3806x over previous
#include <cuda_runtime.h>
#include <cuda_fp16.h>

#define N_NODES 100000
#define N_FEATS 512
#define HIDDEN  64
#define NSAMP   5
#define NCLS    16
#define NBATCH  16384

typedef unsigned int u32;

// ---------------- scratch (static device globals) ---------------------------
__device__ __half g_W1[128 * N_FEATS];   // [n=0..127][k] row-major fp16
__device__ __half g_W2[128 * HIDDEN];
__device__ __half g_Wc[32 * HIDDEN];     // rows 0-15: wcls hi, rows 16-31: wcls lo
__device__ __half g_PG[(size_t)N_NODES * 128];      // P | G  (fp16)
__device__ __half g_UV[(size_t)N_NODES * 128];      // U | V  (fp16)

// ---------------- helpers ----------------------------------------------------
__device__ __forceinline__ u32 smem_u32(const void* p) {
    u32 a;
    asm("{ .reg .u64 t; cvta.to.shared.u64 t, %1; cvt.u32.u64 %0, t; }"
        : "=r"(a) : "l"(p));
    return a;
}
__device__ __forceinline__ void ldsm4(u32& r0, u32& r1, u32& r2, u32& r3, u32 addr) {
    asm volatile("ldmatrix.sync.aligned.m8n8.x4.shared.b16 {%0,%1,%2,%3}, [%4];"
                 : "=r"(r0), "=r"(r1), "=r"(r2), "=r"(r3) : "r"(addr));
}
__device__ __forceinline__ void mma_f16(float* d, const u32* a, const u32* b) {
    asm volatile(
        "mma.sync.aligned.m16n8k16.row.col.f32.f16.f16.f32 "
        "{%0,%1,%2,%3}, {%4,%5,%6,%7}, {%8,%9}, {%0,%1,%2,%3};"
        : "+f"(d[0]), "+f"(d[1]), "+f"(d[2]), "+f"(d[3])
        : "r"(a[0]), "r"(a[1]), "r"(a[2]), "r"(a[3]), "r"(b[0]), "r"(b[1]));
}
__device__ __forceinline__ void cpasync16(u32 dst, const void* src, int srcsize) {
    asm volatile("cp.async.cg.shared.global [%0], [%1], 16, %2;"
                 :: "r"(dst), "l"(src), "r"(srcsize) : "memory");
}
__device__ __forceinline__ void cpcommit() {
    asm volatile("cp.async.commit_group;" ::: "memory");
}
template <int N>
__device__ __forceinline__ void cpwait() {
    asm volatile("cp.async.wait_group %0;" :: "n"(N) : "memory");
}
#define SW128(x) ((x) ^ (((x) >> 3) & 0x70))
#define SW64(x)  ((x) ^ (((x) >> 3) & 0x30))

// ---------------------------------------------------------------------------
// Weight prep: W1/W2 fp16 ([n][k] row-major; n<64 self, n>=64 neighbor block),
// wcls split into fp16 hi/lo rows.
// ---------------------------------------------------------------------------
__global__ void prep_weights(const float* __restrict__ w1, const float* __restrict__ w2,
                             const float* __restrict__ wcls) {
    int idx = blockIdx.x * 256 + threadIdx.x;
    if (idx < 128 * N_FEATS) {
        int n = idx / N_FEATS, k = idx % N_FEATS;
        float v = (n < 64) ? w1[n * (2 * N_FEATS) + k]
                           : w1[(n - 64) * (2 * N_FEATS) + N_FEATS + k];
        g_W1[idx] = __float2half_rn(v);
    }
    if (idx < 128 * HIDDEN) {
        int n = idx / HIDDEN, k = idx % HIDDEN;
        float v = (n < 64) ? w2[n * (2 * HIDDEN) + k]
                           : w2[(n - 64) * (2 * HIDDEN) + HIDDEN + k];
        g_W2[idx] = __float2half_rn(v);
    }
    if (idx < NCLS * HIDDEN) {
        float v = wcls[idx];
        __half h = __float2half_rn(v);
        g_Wc[idx] = h;
        g_Wc[NCLS * HIDDEN + idx] = __float2half_rn(v - __half2float(h));
    }
}

// ===========================================================================
// GEMM1: C[M,128] (fp16) = A[M,512] (fp32, converted in smem) @ W1[128,512]^T
// 128x128 CTA tile, 8 warps (64x32 warp tiles), KC=32.
// Ring: 3 A-fp32 stages, 4 B stages, 2 fp16 work bufs.
// Loop order: sync -> issue -> MMA(t) -> cpwait -> convert(t+1), so tensor
// work overlaps the cp.async arrival instead of serializing behind it.
// ===========================================================================
#define KC1   32
#define NCH1  (N_FEATS / KC1)          // 16
#define A1_OFF   0                      // 3 x 16384
#define A1_BYTES 16384
#define B1_OFF   49152                  // 4 x 8192
#define B1_BYTES 8192
#define W1_OFF   81920                  // 2 x 8192
#define W1_BYTES 8192
#define G1_SMEM  98304                  // 96 KB

__global__ __launch_bounds__(256, 2)
void gemm1_tc(const float* __restrict__ Af, const __half* __restrict__ Bm,
              __half* __restrict__ Cm, int M) {
    extern __shared__ __align__(1024) char smem[];
    const u32 sb = smem_u32(smem);
    const int tid  = threadIdx.x;
    const int wid  = tid >> 5;
    const int lane = tid & 31;
    const int wm   = (wid & 1) * 64;
    const int wn   = (wid >> 1) * 32;
    const int row0 = blockIdx.x * 128;

    const int lrow  = tid >> 1;        // 0..127
    const int lhalf = tid & 1;
    const bool arow_ok = (row0 + lrow) < M;
    const u32 aoff = (u32)lrow * 128 + (u32)lhalf * 64;   // A stage byte offset
    const u32 woff = (u32)lrow * 64 + (u32)lhalf * 32;    // fp16 row byte offset

    auto issue_stage = [&](int c) {
        u32 abase = sb + A1_OFF + (c % 3) * A1_BYTES;
        u32 bbase = sb + B1_OFF + (c & 3) * B1_BYTES;
        int k0 = c * KC1;
        const float* asrc = Af + (size_t)(arow_ok ? row0 + lrow : 0) * N_FEATS
                               + k0 + lhalf * 16;
        int sz = arow_ok ? 16 : 0;
#pragma unroll
        for (int j = 0; j < 4; j++)
            cpasync16(abase + SW128(aoff + j * 16), asrc + j * 4, sz);
        const __half* bsrc = Bm + (size_t)lrow * N_FEATS + k0 + lhalf * 16;
#pragma unroll
        for (int j = 0; j < 2; j++)
            cpasync16(bbase + SW64(woff + j * 16), bsrc + j * 8, 16);
        cpcommit();
    };

    auto convert = [&](int c) {
        char* astage = smem + A1_OFF + (c % 3) * A1_BYTES;
        char* wbase  = smem + W1_OFF + (c & 1) * W1_BYTES;
#pragma unroll
        for (int j = 0; j < 2; j++) {
            float4 v0 = *(const float4*)(astage + SW128(aoff + j * 32));
            float4 v1 = *(const float4*)(astage + SW128(aoff + j * 32 + 16));
            __half2 p0 = __floats2half2_rn(v0.x, v0.y);
            __half2 p1 = __floats2half2_rn(v0.z, v0.w);
            __half2 p2 = __floats2half2_rn(v1.x, v1.y);
            __half2 p3 = __floats2half2_rn(v1.z, v1.w);
            *(uint4*)(wbase + SW64(woff + j * 16)) =
                make_uint4(*(u32*)&p0, *(u32*)&p1, *(u32*)&p2, *(u32*)&p3);
        }
    };

    // ldmatrix lane coords
    const int grp = lane >> 3, lr = lane & 7;
    const int a_m  = wm + (grp & 1) * 8 + lr;
    const int a_kb = (grp >> 1) * 16;
    const int b_n  = wn + (grp >> 1) * 8 + lr;
    const int b_kb = (grp & 1) * 16;

    float acc[4][4][4];
#pragma unroll
    for (int i = 0; i < 4; i++)
#pragma unroll
        for (int j = 0; j < 4; j++)
#pragma unroll
            for (int c = 0; c < 4; c++) acc[i][j][c] = 0.f;

    issue_stage(0);
    issue_stage(1);
    issue_stage(2);
    cpwait<2>();          // chunk 0 arrived
    convert(0);

    for (int t = 0; t < NCH1; ++t) {
        __syncthreads();  // publish wrk[t&1] + B[t]; all reads of t-1 done

        if (t + 3 < NCH1) issue_stage(t + 3);

        // ---- MMA(t) FIRST: its operands were converted last iteration ----
        u32 sW = sb + W1_OFF + (t & 1) * W1_BYTES;
        u32 sB = sb + B1_OFF + (t & 3) * B1_BYTES;

#pragma unroll
        for (int ks = 0; ks < 2; ks++) {
            u32 a4[4][4];
#pragma unroll
            for (int mt = 0; mt < 4; mt++) {
                u32 off = SW64((u32)((a_m + mt * 16) * 64 + ks * 32 + a_kb));
                ldsm4(a4[mt][0], a4[mt][1], a4[mt][2], a4[mt][3], sW + off);
            }
            u32 b4[4][2];
#pragma unroll
            for (int p = 0; p < 2; p++) {
                u32 off = SW64((u32)((b_n + p * 16) * 64 + ks * 32 + b_kb));
                u32 r0, r1, r2, r3;
                ldsm4(r0, r1, r2, r3, sB + off);
                b4[2 * p][0] = r0; b4[2 * p][1] = r1;
                b4[2 * p + 1][0] = r2; b4[2 * p + 1][1] = r3;
            }
#pragma unroll
            for (int mt = 0; mt < 4; mt++)
#pragma unroll
                for (int nt = 0; nt < 4; nt++)
                    mma_f16(acc[mt][nt], a4[mt], b4[nt]);
        }

        // ---- then wait for chunk t+1 and convert it (overlapped w/ MMA) ----
        if (t + 1 < NCH1) {
            if (t + 3 < NCH1)      cpwait<2>();
            else if (t + 2 < NCH1) cpwait<1>();
            else                   cpwait<0>();
            convert(t + 1);
        }
    }

    // epilogue: fp16 output
    const int tm = lane >> 2;
    const int tn = (lane & 3) * 2;
#pragma unroll
    for (int mt = 0; mt < 4; mt++) {
        int gm0 = row0 + wm + mt * 16 + tm;
#pragma unroll
        for (int nt = 0; nt < 4; nt++) {
            int gn = wn + nt * 8 + tn;
            __half2 v01 = __floats2half2_rn(acc[mt][nt][0], acc[mt][nt][1]);
            __half2 v23 = __floats2half2_rn(acc[mt][nt][2], acc[mt][nt][3]);
            if (gm0 < M)     *(__half2*)(Cm + (size_t)gm0 * 128 + gn) = v01;
            if (gm0 + 8 < M) *(__half2*)(Cm + (size_t)(gm0 + 8) * 128 + gn) = v23;
        }
    }
}

// ===========================================================================
// GEMM2 fused with layer-1 aggregation:
//   A[r] = relu(P[n] + 0.2 * sum_s G[neigh[n,s]])  built in smem from g_PG,
//   C[M,128] (fp16) = A[M,64] @ W2[128,64]^T.
// ===========================================================================
#define G2_OFFA 0
#define G2_OFFB 16384
#define G2_SMEM 32768

__global__ __launch_bounds__(256, 2)
void gemm2_fused(const int* __restrict__ neigh, const __half* __restrict__ Bm,
                 __half* __restrict__ Cm, int M) {
    extern __shared__ __align__(1024) char smem[];
    const u32 sb = smem_u32(smem);
    const int tid  = threadIdx.x;
    const int wid  = tid >> 5;
    const int lane = tid & 31;
    const int wm   = (wid & 1) * 64;
    const int wn   = (wid >> 1) * 32;
    const int row0 = blockIdx.x * 128;

    const int lrow  = tid >> 1;
    const int lhalf = tid & 1;
    const u32 rowoff = (u32)lrow * 128 + (u32)lhalf * 64;
    const int n = row0 + lrow;
    const bool arow_ok = n < M;

    // --- B tile via cp.async (overlaps the gather) ---
    {
        u32 bbase = sb + G2_OFFB;
        const __half* bsrc = Bm + (size_t)lrow * HIDDEN + lhalf * 32;
#pragma unroll
        for (int j = 0; j < 4; j++)
            cpasync16(bbase + SW128(rowoff + j * 16), bsrc + j * 8, 16);
        cpcommit();
    }

    // --- A tile: fused aggregation from g_PG (L2-resident) ---
    {
        float val[32];
#pragma unroll
        for (int e = 0; e < 32; e++) val[e] = 0.f;

        if (arow_ok) {
#pragma unroll
            for (int s = 0; s < NSAMP; s++) {
                int nb = __ldg(&neigh[n * NSAMP + s]);
                const uint4* src = (const uint4*)(g_PG + (size_t)nb * 128 + 64 + lhalf * 32);
#pragma unroll
                for (int j = 0; j < 4; j++) {
                    uint4 v = __ldg(src + j);
                    u32 w[4] = {v.x, v.y, v.z, v.w};
#pragma unroll
                    for (int q = 0; q < 4; q++) {
                        __half2 h = *(__half2*)&w[q];
                        val[j * 8 + q * 2]     += __low2float(h);
                        val[j * 8 + q * 2 + 1] += __high2float(h);
                    }
                }
            }
            const uint4* sp = (const uint4*)(g_PG + (size_t)n * 128 + lhalf * 32);
#pragma unroll
            for (int j = 0; j < 4; j++) {
                uint4 v = __ldg(sp + j);
                u32 w[4] = {v.x, v.y, v.z, v.w};
#pragma unroll
                for (int q = 0; q < 4; q++) {
                    __half2 h = *(__half2*)&w[q];
                    int e = j * 8 + q * 2;
                    val[e]     = fmaxf(fmaf(val[e],     0.2f, __low2float(h)),  0.f);
                    val[e + 1] = fmaxf(fmaf(val[e + 1], 0.2f, __high2float(h)), 0.f);
                }
            }
        }

        char* abase = smem + G2_OFFA;
#pragma unroll
        for (int j = 0; j < 4; j++) {
            __half2 p0 = __floats2half2_rn(val[j * 8 + 0], val[j * 8 + 1]);
            __half2 p1 = __floats2half2_rn(val[j * 8 + 2], val[j * 8 + 3]);
            __half2 p2 = __floats2half2_rn(val[j * 8 + 4], val[j * 8 + 5]);
            __half2 p3 = __floats2half2_rn(val[j * 8 + 6], val[j * 8 + 7]);
            *(uint4*)(abase + SW128(rowoff + j * 16)) =
                make_uint4(*(u32*)&p0, *(u32*)&p1, *(u32*)&p2, *(u32*)&p3);
        }
    }

    cpwait<0>();
    __syncthreads();

    const int grp = lane >> 3, lr = lane & 7;
    const int a_m  = wm + (grp & 1) * 8 + lr;
    const int a_kb = (grp >> 1) * 16;
    const int b_n  = wn + (grp >> 1) * 8 + lr;
    const int b_kb = (grp & 1) * 16;

    float acc[4][4][4];
#pragma unroll
    for (int i = 0; i < 4; i++)
#pragma unroll
        for (int j = 0; j < 4; j++)
#pragma unroll
            for (int c = 0; c < 4; c++) acc[i][j][c] = 0.f;

    u32 sA = sb + G2_OFFA, sB = sb + G2_OFFB;
#pragma unroll
    for (int ks = 0; ks < 4; ks++) {
        u32 a4[4][4];
#pragma unroll
        for (int mt = 0; mt < 4; mt++) {
            u32 off = SW128((u32)((a_m + mt * 16) * 128 + ks * 32 + a_kb));
            ldsm4(a4[mt][0], a4[mt][1], a4[mt][2], a4[mt][3], sA + off);
        }
        u32 b4[4][2];
#pragma unroll
        for (int p = 0; p < 2; p++) {
            u32 off = SW128((u32)((b_n + p * 16) * 128 + ks * 32 + b_kb));
            u32 r0, r1, r2, r3;
            ldsm4(r0, r1, r2, r3, sB + off);
            b4[2 * p][0] = r0; b4[2 * p][1] = r1;
            b4[2 * p + 1][0] = r2; b4[2 * p + 1][1] = r3;
        }
#pragma unroll
        for (int mt = 0; mt < 4; mt++)
#pragma unroll
            for (int nt = 0; nt < 4; nt++)
                mma_f16(acc[mt][nt], a4[mt], b4[nt]);
    }

    const int tm = lane >> 2;
    const int tn = (lane & 3) * 2;
#pragma unroll
    for (int mt = 0; mt < 4; mt++) {
        int gm0 = row0 + wm + mt * 16 + tm;
#pragma unroll
        for (int nt = 0; nt < 4; nt++) {
            int gn = wn + nt * 8 + tn;
            __half2 v01 = __floats2half2_rn(acc[mt][nt][0], acc[mt][nt][1]);
            __half2 v23 = __floats2half2_rn(acc[mt][nt][2], acc[mt][nt][3]);
            if (gm0 < M)     *(__half2*)(Cm + (size_t)gm0 * 128 + gn) = v01;
            if (gm0 + 8 < M) *(__half2*)(Cm + (size_t)(gm0 + 8) * 128 + gn) = v23;
        }
    }
}

// ===========================================================================
// Final fused: h2 = relu(U[n] + 0.2*sum_s V[nb]) -> [64,64] fp16 smem tile,
// out[64,16] = h2 @ (Wc_hi + Wc_lo)^T via HMMA. 256 CTAs x 256 thr
// (64 batch rows per CTA -> grid covers all 148 SMs).
// ===========================================================================
#define FN_OFFA 0
#define FN_OFFB 8192
#define FN_SMEM 12288

__global__ __launch_bounds__(256)
void final_fused(const int* __restrict__ nodes, const int* __restrict__ neigh,
                 float* __restrict__ out) {
    extern __shared__ __align__(1024) char smem[];
    const u32 sb = smem_u32(smem);
    const int tid  = threadIdx.x;
    const int wid  = tid >> 5;
    const int lane = tid & 31;
    const int row0 = blockIdx.x * 64;

    // --- B: wcls hi/lo, 32 rows x 128B, via cp.async ---
    if (tid < 64) {
        int r = tid >> 1, h = tid & 1;
        const __half* src = g_Wc + r * HIDDEN + h * 32;
        u32 bbase = sb + FN_OFFB;
        u32 roff = (u32)r * 128 + (u32)h * 64;
#pragma unroll
        for (int j = 0; j < 4; j++)
            cpasync16(bbase + SW128(roff + j * 16), src + j * 8, 16);
    }
    cpcommit();

    // --- A: gather + aggregate h2 row (4 threads per element, 16 vals each) ---
    {
        const int lrow  = tid >> 2;          // 0..63
        const int lhalf = tid & 3;           // 16 fp16 each
        const int b = row0 + lrow;
        const int n = __ldg(&nodes[b]);

        float val[16];
#pragma unroll
        for (int e = 0; e < 16; e++) val[e] = 0.f;

#pragma unroll
        for (int s = 0; s < NSAMP; s++) {
            int nb = __ldg(&neigh[n * NSAMP + s]);
            const uint4* src = (const uint4*)(g_UV + (size_t)nb * 128 + 64 + lhalf * 16);
#pragma unroll
            for (int j = 0; j < 2; j++) {
                uint4 v = __ldg(src + j);
                u32 w[4] = {v.x, v.y, v.z, v.w};
#pragma unroll
                for (int q = 0; q < 4; q++) {
                    __half2 hh = *(__half2*)&w[q];
                    val[j * 8 + q * 2]     += __low2float(hh);
                    val[j * 8 + q * 2 + 1] += __high2float(hh);
                }
            }
        }
        const uint4* sp = (const uint4*)(g_UV + (size_t)n * 128 + lhalf * 16);
#pragma unroll
        for (int j = 0; j < 2; j++) {
            uint4 v = __ldg(sp + j);
            u32 w[4] = {v.x, v.y, v.z, v.w};
#pragma unroll
            for (int q = 0; q < 4; q++) {
                __half2 hh = *(__half2*)&w[q];
                int e = j * 8 + q * 2;
                val[e]     = fmaxf(fmaf(val[e],     0.2f, __low2float(hh)),  0.f);
                val[e + 1] = fmaxf(fmaf(val[e + 1], 0.2f, __high2float(hh)), 0.f);
            }
        }

        char* abase = smem + FN_OFFA;
        u32 roff = (u32)lrow * 128 + (u32)lhalf * 32;
#pragma unroll
        for (int j = 0; j < 2; j++) {
            __half2 p0 = __floats2half2_rn(val[j * 8 + 0], val[j * 8 + 1]);
            __half2 p1 = __floats2half2_rn(val[j * 8 + 2], val[j * 8 + 3]);
            __half2 p2 = __floats2half2_rn(val[j * 8 + 4], val[j * 8 + 5]);
            __half2 p3 = __floats2half2_rn(val[j * 8 + 6], val[j * 8 + 7]);
            *(uint4*)(abase + SW128(roff + j * 16)) =
                make_uint4(*(u32*)&p0, *(u32*)&p1, *(u32*)&p2, *(u32*)&p3);
        }
    }

    cpwait<0>();
    __syncthreads();

    // --- MMA: warps 0-3 handle 16 rows each, all 16 classes ---
    if (wid < 4) {
        const int grp = lane >> 3, lr = lane & 7;
        const int a_m  = wid * 16 + (grp & 1) * 8 + lr;
        const int a_kb = (grp >> 1) * 16;
        const int b_n  = (grp >> 1) * 8 + lr;
        const int b_kb = (grp & 1) * 16;

        float acc[2][4];
#pragma unroll
        for (int i = 0; i < 2; i++)
#pragma unroll
            for (int c = 0; c < 4; c++) acc[i][c] = 0.f;

        u32 sA = sb + FN_OFFA, sB = sb + FN_OFFB;
#pragma unroll
        for (int ks = 0; ks < 4; ks++) {
            u32 a4[4];
            {
                u32 off = SW128((u32)(a_m * 128 + ks * 32 + a_kb));
                ldsm4(a4[0], a4[1], a4[2], a4[3], sA + off);
            }
            u32 bh[2][2], bl[2][2];
            {
                u32 off = SW128((u32)(b_n * 128 + ks * 32 + b_kb));
                u32 r0, r1, r2, r3;
                ldsm4(r0, r1, r2, r3, sB + off);
                bh[0][0] = r0; bh[0][1] = r1; bh[1][0] = r2; bh[1][1] = r3;
                ldsm4(r0, r1, r2, r3, sB + 2048 + off);
                bl[0][0] = r0; bl[0][1] = r1; bl[1][0] = r2; bl[1][1] = r3;
            }
#pragma unroll
            for (int nt = 0; nt < 2; nt++) {
                mma_f16(acc[nt], a4, bh[nt]);
                mma_f16(acc[nt], a4, bl[nt]);
            }
        }

        const int tm = lane >> 2;
        const int tn = (lane & 3) * 2;
        int gm0 = row0 + wid * 16 + tm;
#pragma unroll
        for (int nt = 0; nt < 2; nt++) {
            int gn = nt * 8 + tn;
            *(float2*)(out + (size_t)gm0 * NCLS + gn)       = make_float2(acc[nt][0], acc[nt][1]);
            *(float2*)(out + (size_t)(gm0 + 8) * NCLS + gn) = make_float2(acc[nt][2], acc[nt][3]);
        }
    }
}

// ---------------------------------------------------------------------------
extern "C" void kernel_launch(void* const* d_in, const int* in_sizes, int n_in,
                              void* d_out, int out_size) {
    const float* features = (const float*)d_in[0];
    const float* w1       = (const float*)d_in[1];
    const float* w2       = (const float*)d_in[2];
    const float* wcls     = (const float*)d_in[3];
    const int*   nodes    = (const int*)d_in[4];
    const int*   neigh    = (const int*)d_in[5];
    float*       out      = (float*)d_out;

    __half *pW1, *pW2, *pPG, *pUV;
    cudaGetSymbolAddress((void**)&pW1, g_W1);
    cudaGetSymbolAddress((void**)&pW2, g_W2);
    cudaGetSymbolAddress((void**)&pPG, g_PG);
    cudaGetSymbolAddress((void**)&pUV, g_UV);

    cudaFuncSetAttribute(gemm1_tc, cudaFuncAttributeMaxDynamicSharedMemorySize, G1_SMEM);
    cudaFuncSetAttribute(gemm2_fused, cudaFuncAttributeMaxDynamicSharedMemorySize, G2_SMEM);
    cudaFuncSetAttribute(final_fused, cudaFuncAttributeMaxDynamicSharedMemorySize, FN_SMEM);

    const int gemm_blocks = (N_NODES + 127) / 128;   // 782

    prep_weights<<<(128 * N_FEATS + 255) / 256, 256>>>(w1, w2, wcls);
    gemm1_tc<<<gemm_blocks, 256, G1_SMEM>>>(features, pW1, pPG, N_NODES);
    gemm2_fused<<<gemm_blocks, 256, G2_SMEM>>>(neigh, pW2, pUV, N_NODES);
    final_fused<<<NBATCH / 64, 256, FN_SMEM>>>(nodes, neigh, out);
}

// round 12
// speedup vs baseline: 1.3872x; 1.0048x over previous
#include <cuda_runtime.h>
#include <cuda_fp16.h>

#define N_NODES 100000
#define N_FEATS 512
#define HIDDEN  64
#define NSAMP   5
#define NCLS    16
#define NBATCH  16384

typedef unsigned int u32;

// ---------------- scratch (static device globals) ---------------------------
__device__ __half g_W1[128 * N_FEATS];   // [n=0..127][k] row-major fp16
__device__ __half g_W2[128 * HIDDEN];
__device__ __half g_Wc[32 * HIDDEN];     // rows 0-15: wcls hi, rows 16-31: wcls lo
__device__ __half g_PG[(size_t)N_NODES * 128];      // P | G  (fp16)
__device__ __half g_UV[(size_t)N_NODES * 128];      // U | V  (fp16)

// ---------------- helpers ----------------------------------------------------
__device__ __forceinline__ u32 smem_u32(const void* p) {
    u32 a;
    asm("{ .reg .u64 t; cvta.to.shared.u64 t, %1; cvt.u32.u64 %0, t; }"
        : "=r"(a) : "l"(p));
    return a;
}
__device__ __forceinline__ void ldsm4(u32& r0, u32& r1, u32& r2, u32& r3, u32 addr) {
    asm volatile("ldmatrix.sync.aligned.m8n8.x4.shared.b16 {%0,%1,%2,%3}, [%4];"
                 : "=r"(r0), "=r"(r1), "=r"(r2), "=r"(r3) : "r"(addr));
}
__device__ __forceinline__ void mma_f16(float* d, const u32* a, const u32* b) {
    asm volatile(
        "mma.sync.aligned.m16n8k16.row.col.f32.f16.f16.f32 "
        "{%0,%1,%2,%3}, {%4,%5,%6,%7}, {%8,%9}, {%0,%1,%2,%3};"
        : "+f"(d[0]), "+f"(d[1]), "+f"(d[2]), "+f"(d[3])
        : "r"(a[0]), "r"(a[1]), "r"(a[2]), "r"(a[3]), "r"(b[0]), "r"(b[1]));
}
__device__ __forceinline__ void cpasync16(u32 dst, const void* src, int srcsize) {
    asm volatile("cp.async.cg.shared.global [%0], [%1], 16, %2;"
                 :: "r"(dst), "l"(src), "r"(srcsize) : "memory");
}
__device__ __forceinline__ void cpcommit() {
    asm volatile("cp.async.commit_group;" ::: "memory");
}
template <int N>
__device__ __forceinline__ void cpwait() {
    asm volatile("cp.async.wait_group %0;" :: "n"(N) : "memory");
}
#define SW128(x) ((x) ^ (((x) >> 3) & 0x70))
#define SW64(x)  ((x) ^ (((x) >> 3) & 0x30))

// ---------------------------------------------------------------------------
// Weight prep: W1/W2 fp16 ([n][k] row-major; n<64 self, n>=64 neighbor block),
// wcls split into fp16 hi/lo rows.
// ---------------------------------------------------------------------------
__global__ void prep_weights(const float* __restrict__ w1, const float* __restrict__ w2,
                             const float* __restrict__ wcls) {
    int idx = blockIdx.x * 256 + threadIdx.x;
    if (idx < 128 * N_FEATS) {
        int n = idx / N_FEATS, k = idx % N_FEATS;
        float v = (n < 64) ? w1[n * (2 * N_FEATS) + k]
                           : w1[(n - 64) * (2 * N_FEATS) + N_FEATS + k];
        g_W1[idx] = __float2half_rn(v);
    }
    if (idx < 128 * HIDDEN) {
        int n = idx / HIDDEN, k = idx % HIDDEN;
        float v = (n < 64) ? w2[n * (2 * HIDDEN) + k]
                           : w2[(n - 64) * (2 * HIDDEN) + HIDDEN + k];
        g_W2[idx] = __float2half_rn(v);
    }
    if (idx < NCLS * HIDDEN) {
        float v = wcls[idx];
        __half h = __float2half_rn(v);
        g_Wc[idx] = h;
        g_Wc[NCLS * HIDDEN + idx] = __float2half_rn(v - __half2float(h));
    }
}

// ===========================================================================
// GEMM1: C[M,128] (fp16) = A[M,512] (fp32) @ W1[128,512]^T
// 128x128 CTA tile, 8 warps (64x32 warp tiles), KC=32.
// A path: LDG fp32 -> registers (issued 1 chunk ahead) -> convert -> STS fp16.
// No fp32 smem staging. B: 4-stage cp.async ring. 2 fp16 work buffers.
// Loop: sync -> issueB(t+3) -> LDG A(t+1) -> MMA(t) -> convert/STS(t+1) -> cpwait.
// ===========================================================================
#define KC1   32
#define NCH1  (N_FEATS / KC1)          // 16
#define B1_OFF   0                      // 4 x 8192
#define B1_BYTES 8192
#define W1_OFF   32768                  // 2 x 8192
#define W1_BYTES 8192
#define G1_SMEM  49152                  // 48 KB

__global__ __launch_bounds__(256, 2)
void gemm1_tc(const float* __restrict__ Af, const __half* __restrict__ Bm,
              __half* __restrict__ Cm, int M) {
    extern __shared__ __align__(1024) char smem[];
    const u32 sb = smem_u32(smem);
    const int tid  = threadIdx.x;
    const int wid  = tid >> 5;
    const int lane = tid & 31;
    const int wm   = (wid & 1) * 64;
    const int wn   = (wid >> 1) * 32;
    const int row0 = blockIdx.x * 128;

    const int lrow  = tid >> 1;        // 0..127
    const int lhalf = tid & 1;
    // clamp OOB rows to row 0: garbage only pollutes C rows >= M (not stored)
    const int arow = (row0 + lrow < M) ? (row0 + lrow) : 0;
    const u32 woff = (u32)lrow * 64 + (u32)lhalf * 32;    // fp16 row byte offset

    const float* abase_g = Af + (size_t)arow * N_FEATS + lhalf * 16;

    auto issueB = [&](int c) {
        u32 bbase = sb + B1_OFF + (c & 3) * B1_BYTES;
        const __half* bsrc = Bm + (size_t)lrow * N_FEATS + c * KC1 + lhalf * 16;
#pragma unroll
        for (int j = 0; j < 2; j++)
            cpasync16(bbase + SW64(woff + j * 16), bsrc + j * 8, 16);
        cpcommit();
    };

    float4 araw[4];
    auto ldgA = [&](int c) {
        const float4* src = (const float4*)(abase_g + c * KC1);
#pragma unroll
        for (int j = 0; j < 4; j++) araw[j] = __ldg(src + j);
    };
    auto convert_sts = [&](int c) {
        char* wbase = smem + W1_OFF + (c & 1) * W1_BYTES;
#pragma unroll
        for (int j = 0; j < 2; j++) {
            float4 v0 = araw[2 * j];
            float4 v1 = araw[2 * j + 1];
            __half2 p0 = __floats2half2_rn(v0.x, v0.y);
            __half2 p1 = __floats2half2_rn(v0.z, v0.w);
            __half2 p2 = __floats2half2_rn(v1.x, v1.y);
            __half2 p3 = __floats2half2_rn(v1.z, v1.w);
            *(uint4*)(wbase + SW64(woff + j * 16)) =
                make_uint4(*(u32*)&p0, *(u32*)&p1, *(u32*)&p2, *(u32*)&p3);
        }
    };

    // ldmatrix lane coords
    const int grp = lane >> 3, lr = lane & 7;
    const int a_m  = wm + (grp & 1) * 8 + lr;
    const int a_kb = (grp >> 1) * 16;
    const int b_n  = wn + (grp >> 1) * 8 + lr;
    const int b_kb = (grp & 1) * 16;

    float acc[4][4][4];
#pragma unroll
    for (int i = 0; i < 4; i++)
#pragma unroll
        for (int j = 0; j < 4; j++)
#pragma unroll
            for (int c = 0; c < 4; c++) acc[i][j][c] = 0.f;

    // prologue
    ldgA(0);
    issueB(0);
    issueB(1);
    issueB(2);
    convert_sts(0);       // wrk0 <- chunk 0 (own-thread regs; LDG dependency)
    cpwait<2>();          // B(0) arrived

    for (int t = 0; t < NCH1; ++t) {
        __syncthreads();  // publish wrk[t&1] + B(t); prior reads done

        if (t + 3 < NCH1) issueB(t + 3);
        if (t + 1 < NCH1) ldgA(t + 1);      // in-flight during MMA(t)

        // ---- MMA(t): operands converted/arrived last iteration ----
        u32 sW = sb + W1_OFF + (t & 1) * W1_BYTES;
        u32 sB = sb + B1_OFF + (t & 3) * B1_BYTES;

#pragma unroll
        for (int ks = 0; ks < 2; ks++) {
            u32 a4[4][4];
#pragma unroll
            for (int mt = 0; mt < 4; mt++) {
                u32 off = SW64((u32)((a_m + mt * 16) * 64 + ks * 32 + a_kb));
                ldsm4(a4[mt][0], a4[mt][1], a4[mt][2], a4[mt][3], sW + off);
            }
            u32 b4[4][2];
#pragma unroll
            for (int p = 0; p < 2; p++) {
                u32 off = SW64((u32)((b_n + p * 16) * 64 + ks * 32 + b_kb));
                u32 r0, r1, r2, r3;
                ldsm4(r0, r1, r2, r3, sB + off);
                b4[2 * p][0] = r0; b4[2 * p][1] = r1;
                b4[2 * p + 1][0] = r2; b4[2 * p + 1][1] = r3;
            }
#pragma unroll
            for (int mt = 0; mt < 4; mt++)
#pragma unroll
                for (int nt = 0; nt < 4; nt++)
                    mma_f16(acc[mt][nt], a4[mt], b4[nt]);
        }

        // ---- convert chunk t+1 (LDG latency hidden by MMA), then B wait ----
        if (t + 1 < NCH1) {
            convert_sts(t + 1);             // writes wrk[(t+1)&1]: free since sync
            if (t + 3 < NCH1)      cpwait<2>();
            else if (t + 2 < NCH1) cpwait<1>();
            else                   cpwait<0>();
        }
    }

    // epilogue: fp16 output
    const int tm = lane >> 2;
    const int tn = (lane & 3) * 2;
#pragma unroll
    for (int mt = 0; mt < 4; mt++) {
        int gm0 = row0 + wm + mt * 16 + tm;
#pragma unroll
        for (int nt = 0; nt < 4; nt++) {
            int gn = wn + nt * 8 + tn;
            __half2 v01 = __floats2half2_rn(acc[mt][nt][0], acc[mt][nt][1]);
            __half2 v23 = __floats2half2_rn(acc[mt][nt][2], acc[mt][nt][3]);
            if (gm0 < M)     *(__half2*)(Cm + (size_t)gm0 * 128 + gn) = v01;
            if (gm0 + 8 < M) *(__half2*)(Cm + (size_t)(gm0 + 8) * 128 + gn) = v23;
        }
    }
}

// ===========================================================================
// GEMM2 fused with layer-1 aggregation:
//   A[r] = relu(P[n] + 0.2 * sum_s G[neigh[n,s]])  built in smem from g_PG,
//   C[M,128] (fp16) = A[M,64] @ W2[128,64]^T.
// ===========================================================================
#define G2_OFFA 0
#define G2_OFFB 16384
#define G2_SMEM 32768

__global__ __launch_bounds__(256, 2)
void gemm2_fused(const int* __restrict__ neigh, const __half* __restrict__ Bm,
                 __half* __restrict__ Cm, int M) {
    extern __shared__ __align__(1024) char smem[];
    const u32 sb = smem_u32(smem);
    const int tid  = threadIdx.x;
    const int wid  = tid >> 5;
    const int lane = tid & 31;
    const int wm   = (wid & 1) * 64;
    const int wn   = (wid >> 1) * 32;
    const int row0 = blockIdx.x * 128;

    const int lrow  = tid >> 1;
    const int lhalf = tid & 1;
    const u32 rowoff = (u32)lrow * 128 + (u32)lhalf * 64;
    const int n = row0 + lrow;
    const bool arow_ok = n < M;

    // --- B tile via cp.async (overlaps the gather) ---
    {
        u32 bbase = sb + G2_OFFB;
        const __half* bsrc = Bm + (size_t)lrow * HIDDEN + lhalf * 32;
#pragma unroll
        for (int j = 0; j < 4; j++)
            cpasync16(bbase + SW128(rowoff + j * 16), bsrc + j * 8, 16);
        cpcommit();
    }

    // --- A tile: fused aggregation from g_PG (L2-resident) ---
    {
        float val[32];
#pragma unroll
        for (int e = 0; e < 32; e++) val[e] = 0.f;

        if (arow_ok) {
#pragma unroll
            for (int s = 0; s < NSAMP; s++) {
                int nb = __ldg(&neigh[n * NSAMP + s]);
                const uint4* src = (const uint4*)(g_PG + (size_t)nb * 128 + 64 + lhalf * 32);
#pragma unroll
                for (int j = 0; j < 4; j++) {
                    uint4 v = __ldg(src + j);
                    u32 w[4] = {v.x, v.y, v.z, v.w};
#pragma unroll
                    for (int q = 0; q < 4; q++) {
                        __half2 h = *(__half2*)&w[q];
                        val[j * 8 + q * 2]     += __low2float(h);
                        val[j * 8 + q * 2 + 1] += __high2float(h);
                    }
                }
            }
            const uint4* sp = (const uint4*)(g_PG + (size_t)n * 128 + lhalf * 32);
#pragma unroll
            for (int j = 0; j < 4; j++) {
                uint4 v = __ldg(sp + j);
                u32 w[4] = {v.x, v.y, v.z, v.w};
#pragma unroll
                for (int q = 0; q < 4; q++) {
                    __half2 h = *(__half2*)&w[q];
                    int e = j * 8 + q * 2;
                    val[e]     = fmaxf(fmaf(val[e],     0.2f, __low2float(h)),  0.f);
                    val[e + 1] = fmaxf(fmaf(val[e + 1], 0.2f, __high2float(h)), 0.f);
                }
            }
        }

        char* abase = smem + G2_OFFA;
#pragma unroll
        for (int j = 0; j < 4; j++) {
            __half2 p0 = __floats2half2_rn(val[j * 8 + 0], val[j * 8 + 1]);
            __half2 p1 = __floats2half2_rn(val[j * 8 + 2], val[j * 8 + 3]);
            __half2 p2 = __floats2half2_rn(val[j * 8 + 4], val[j * 8 + 5]);
            __half2 p3 = __floats2half2_rn(val[j * 8 + 6], val[j * 8 + 7]);
            *(uint4*)(abase + SW128(rowoff + j * 16)) =
                make_uint4(*(u32*)&p0, *(u32*)&p1, *(u32*)&p2, *(u32*)&p3);
        }
    }

    cpwait<0>();
    __syncthreads();

    const int grp = lane >> 3, lr = lane & 7;
    const int a_m  = wm + (grp & 1) * 8 + lr;
    const int a_kb = (grp >> 1) * 16;
    const int b_n  = wn + (grp >> 1) * 8 + lr;
    const int b_kb = (grp & 1) * 16;

    float acc[4][4][4];
#pragma unroll
    for (int i = 0; i < 4; i++)
#pragma unroll
        for (int j = 0; j < 4; j++)
#pragma unroll
            for (int c = 0; c < 4; c++) acc[i][j][c] = 0.f;

    u32 sA = sb + G2_OFFA, sB = sb + G2_OFFB;
#pragma unroll
    for (int ks = 0; ks < 4; ks++) {
        u32 a4[4][4];
#pragma unroll
        for (int mt = 0; mt < 4; mt++) {
            u32 off = SW128((u32)((a_m + mt * 16) * 128 + ks * 32 + a_kb));
            ldsm4(a4[mt][0], a4[mt][1], a4[mt][2], a4[mt][3], sA + off);
        }
        u32 b4[4][2];
#pragma unroll
        for (int p = 0; p < 2; p++) {
            u32 off = SW128((u32)((b_n + p * 16) * 128 + ks * 32 + b_kb));
            u32 r0, r1, r2, r3;
            ldsm4(r0, r1, r2, r3, sB + off);
            b4[2 * p][0] = r0; b4[2 * p][1] = r1;
            b4[2 * p + 1][0] = r2; b4[2 * p + 1][1] = r3;
        }
#pragma unroll
        for (int mt = 0; mt < 4; mt++)
#pragma unroll
            for (int nt = 0; nt < 4; nt++)
                mma_f16(acc[mt][nt], a4[mt], b4[nt]);
    }

    const int tm = lane >> 2;
    const int tn = (lane & 3) * 2;
#pragma unroll
    for (int mt = 0; mt < 4; mt++) {
        int gm0 = row0 + wm + mt * 16 + tm;
#pragma unroll
        for (int nt = 0; nt < 4; nt++) {
            int gn = wn + nt * 8 + tn;
            __half2 v01 = __floats2half2_rn(acc[mt][nt][0], acc[mt][nt][1]);
            __half2 v23 = __floats2half2_rn(acc[mt][nt][2], acc[mt][nt][3]);
            if (gm0 < M)     *(__half2*)(Cm + (size_t)gm0 * 128 + gn) = v01;
            if (gm0 + 8 < M) *(__half2*)(Cm + (size_t)(gm0 + 8) * 128 + gn) = v23;
        }
    }
}

// ===========================================================================
// Final fused: h2 = relu(U[n] + 0.2*sum_s V[nb]) -> [64,64] fp16 smem tile,
// out[64,16] = h2 @ (Wc_hi + Wc_lo)^T via HMMA. 256 CTAs x 256 thr.
// ===========================================================================
#define FN_OFFA 0
#define FN_OFFB 8192
#define FN_SMEM 12288

__global__ __launch_bounds__(256)
void final_fused(const int* __restrict__ nodes, const int* __restrict__ neigh,
                 float* __restrict__ out) {
    extern __shared__ __align__(1024) char smem[];
    const u32 sb = smem_u32(smem);
    const int tid  = threadIdx.x;
    const int wid  = tid >> 5;
    const int lane = tid & 31;
    const int row0 = blockIdx.x * 64;

    // --- B: wcls hi/lo, 32 rows x 128B, via cp.async ---
    if (tid < 64) {
        int r = tid >> 1, h = tid & 1;
        const __half* src = g_Wc + r * HIDDEN + h * 32;
        u32 bbase = sb + FN_OFFB;
        u32 roff = (u32)r * 128 + (u32)h * 64;
#pragma unroll
        for (int j = 0; j < 4; j++)
            cpasync16(bbase + SW128(roff + j * 16), src + j * 8, 16);
    }
    cpcommit();

    // --- A: gather + aggregate h2 row (4 threads per element, 16 vals each) ---
    {
        const int lrow  = tid >> 2;          // 0..63
        const int lhalf = tid & 3;           // 16 fp16 each
        const int b = row0 + lrow;
        const int n = __ldg(&nodes[b]);

        float val[16];
#pragma unroll
        for (int e = 0; e < 16; e++) val[e] = 0.f;

#pragma unroll
        for (int s = 0; s < NSAMP; s++) {
            int nb = __ldg(&neigh[n * NSAMP + s]);
            const uint4* src = (const uint4*)(g_UV + (size_t)nb * 128 + 64 + lhalf * 16);
#pragma unroll
            for (int j = 0; j < 2; j++) {
                uint4 v = __ldg(src + j);
                u32 w[4] = {v.x, v.y, v.z, v.w};
#pragma unroll
                for (int q = 0; q < 4; q++) {
                    __half2 hh = *(__half2*)&w[q];
                    val[j * 8 + q * 2]     += __low2float(hh);
                    val[j * 8 + q * 2 + 1] += __high2float(hh);
                }
            }
        }
        const uint4* sp = (const uint4*)(g_UV + (size_t)n * 128 + lhalf * 16);
#pragma unroll
        for (int j = 0; j < 2; j++) {
            uint4 v = __ldg(sp + j);
            u32 w[4] = {v.x, v.y, v.z, v.w};
#pragma unroll
            for (int q = 0; q < 4; q++) {
                __half2 hh = *(__half2*)&w[q];
                int e = j * 8 + q * 2;
                val[e]     = fmaxf(fmaf(val[e],     0.2f, __low2float(hh)),  0.f);
                val[e + 1] = fmaxf(fmaf(val[e + 1], 0.2f, __high2float(hh)), 0.f);
            }
        }

        char* abase = smem + FN_OFFA;
        u32 roff = (u32)lrow * 128 + (u32)lhalf * 32;
#pragma unroll
        for (int j = 0; j < 2; j++) {
            __half2 p0 = __floats2half2_rn(val[j * 8 + 0], val[j * 8 + 1]);
            __half2 p1 = __floats2half2_rn(val[j * 8 + 2], val[j * 8 + 3]);
            __half2 p2 = __floats2half2_rn(val[j * 8 + 4], val[j * 8 + 5]);
            __half2 p3 = __floats2half2_rn(val[j * 8 + 6], val[j * 8 + 7]);
            *(uint4*)(abase + SW128(roff + j * 16)) =
                make_uint4(*(u32*)&p0, *(u32*)&p1, *(u32*)&p2, *(u32*)&p3);
        }
    }

    cpwait<0>();
    __syncthreads();

    // --- MMA: warps 0-3 handle 16 rows each, all 16 classes ---
    if (wid < 4) {
        const int grp = lane >> 3, lr = lane & 7;
        const int a_m  = wid * 16 + (grp & 1) * 8 + lr;
        const int a_kb = (grp >> 1) * 16;
        const int b_n  = (grp >> 1) * 8 + lr;
        const int b_kb = (grp & 1) * 16;

        float acc[2][4];
#pragma unroll
        for (int i = 0; i < 2; i++)
#pragma unroll
            for (int c = 0; c < 4; c++) acc[i][c] = 0.f;

        u32 sA = sb + FN_OFFA, sB = sb + FN_OFFB;
#pragma unroll
        for (int ks = 0; ks < 4; ks++) {
            u32 a4[4];
            {
                u32 off = SW128((u32)(a_m * 128 + ks * 32 + a_kb));
                ldsm4(a4[0], a4[1], a4[2], a4[3], sA + off);
            }
            u32 bh[2][2], bl[2][2];
            {
                u32 off = SW128((u32)(b_n * 128 + ks * 32 + b_kb));
                u32 r0, r1, r2, r3;
                ldsm4(r0, r1, r2, r3, sB + off);
                bh[0][0] = r0; bh[0][1] = r1; bh[1][0] = r2; bh[1][1] = r3;
                ldsm4(r0, r1, r2, r3, sB + 2048 + off);
                bl[0][0] = r0; bl[0][1] = r1; bl[1][0] = r2; bl[1][1] = r3;
            }
#pragma unroll
            for (int nt = 0; nt < 2; nt++) {
                mma_f16(acc[nt], a4, bh[nt]);
                mma_f16(acc[nt], a4, bl[nt]);
            }
        }

        const int tm = lane >> 2;
        const int tn = (lane & 3) * 2;
        int gm0 = row0 + wid * 16 + tm;
#pragma unroll
        for (int nt = 0; nt < 2; nt++) {
            int gn = nt * 8 + tn;
            *(float2*)(out + (size_t)gm0 * NCLS + gn)       = make_float2(acc[nt][0], acc[nt][1]);
            *(float2*)(out + (size_t)(gm0 + 8) * NCLS + gn) = make_float2(acc[nt][2], acc[nt][3]);
        }
    }
}

// ---------------------------------------------------------------------------
extern "C" void kernel_launch(void* const* d_in, const int* in_sizes, int n_in,
                              void* d_out, int out_size) {
    const float* features = (const float*)d_in[0];
    const float* w1       = (const float*)d_in[1];
    const float* w2       = (const float*)d_in[2];
    const float* wcls     = (const float*)d_in[3];
    const int*   nodes    = (const int*)d_in[4];
    const int*   neigh    = (const int*)d_in[5];
    float*       out      = (float*)d_out;

    __half *pW1, *pW2, *pPG, *pUV;
    cudaGetSymbolAddress((void**)&pW1, g_W1);
    cudaGetSymbolAddress((void**)&pW2, g_W2);
    cudaGetSymbolAddress((void**)&pPG, g_PG);
    cudaGetSymbolAddress((void**)&pUV, g_UV);

    cudaFuncSetAttribute(gemm1_tc, cudaFuncAttributeMaxDynamicSharedMemorySize, G1_SMEM);
    cudaFuncSetAttribute(gemm2_fused, cudaFuncAttributeMaxDynamicSharedMemorySize, G2_SMEM);
    cudaFuncSetAttribute(final_fused, cudaFuncAttributeMaxDynamicSharedMemorySize, FN_SMEM);

    const int gemm_blocks = (N_NODES + 127) / 128;   // 782

    prep_weights<<<(128 * N_FEATS + 255) / 256, 256>>>(w1, w2, wcls);
    gemm1_tc<<<gemm_blocks, 256, G1_SMEM>>>(features, pW1, pPG, N_NODES);
    gemm2_fused<<<gemm_blocks, 256, G2_SMEM>>>(neigh, pW2, pUV, N_NODES);
    final_fused<<<NBATCH / 64, 256, FN_SMEM>>>(nodes, neigh, out);
}